// round 13
// baseline (speedup 1.0000x reference)
#include <cuda_runtime.h>
#include <math.h>
#include <stdint.h>

#define Nn 50000
#define Ee 1600000
#define EPn 1650000   // Ee + Nn (self loops appended)
#define F 128         // H*C = 4*32
#define NBLK 49       // ceil(Nn/1024) for scan

// ---------------- scratch (static device memory; no allocation) ----------------
__device__ float    g_xl [(size_t)Nn * F];
__device__ float    g_xr [(size_t)Nn * F];
__device__ float    g_h  [(size_t)Nn * F];
__device__ int      g_count[Nn];
__device__ int      g_offs [Nn + 1];
__device__ int      g_cur  [Nn];
__device__ int      g_bsum [64];
__device__ float2   g_sedge[EPn];      // sorted (src_as_float_bits, weight)
__device__ float    g_partial[1024];
__device__ float    g_meanw;

// ---------------- mean(edge_weight), deterministic two-pass ----------------
__global__ void reduce_partial(const float* __restrict__ ew) {
    __shared__ float s[256];
    float acc = 0.f;
    for (int i = blockIdx.x * 256 + threadIdx.x; i < Ee; i += 1024 * 256)
        acc += ew[i];
    s[threadIdx.x] = acc;
    __syncthreads();
    for (int o = 128; o > 0; o >>= 1) {
        if (threadIdx.x < o) s[threadIdx.x] += s[threadIdx.x + o];
        __syncthreads();
    }
    if (threadIdx.x == 0) g_partial[blockIdx.x] = s[0];
}

__global__ void reduce_final() {
    __shared__ float s[1024];
    s[threadIdx.x] = g_partial[threadIdx.x];
    __syncthreads();
    for (int o = 512; o > 0; o >>= 1) {
        if (threadIdx.x < o) s[threadIdx.x] += s[threadIdx.x + o];
        __syncthreads();
    }
    if (threadIdx.x == 0) g_meanw = s[0] / (float)Ee;
}

// ---------------- CSR build: histogram -> scan -> scatter ----------------
__global__ void hist_kernel(const int* __restrict__ dst) {
    int e = blockIdx.x * 256 + threadIdx.x;
    if (e >= EPn) return;
    int d = (e < Ee) ? dst[e] : (e - Ee);
    atomicAdd(&g_count[d], 1);
}

__global__ void scan1_kernel() {      // grid NBLK, block 1024
    __shared__ int s[1024];
    int t = threadIdx.x;
    int i = blockIdx.x * 1024 + t;
    int v = (i < Nn) ? g_count[i] : 0;
    s[t] = v;
    __syncthreads();
    #pragma unroll
    for (int o = 1; o < 1024; o <<= 1) {
        int tmp = (t >= o) ? s[t - o] : 0;
        __syncthreads();
        s[t] += tmp;
        __syncthreads();
    }
    if (i < Nn) g_offs[i] = s[t] - v;           // exclusive within block
    if (t == 1023) g_bsum[blockIdx.x] = s[1023];
}

__global__ void scan2_kernel() {      // 1 block, 64 threads
    __shared__ int s[64];
    int t = threadIdx.x;
    int v = (t < NBLK) ? g_bsum[t] : 0;
    s[t] = v;
    __syncthreads();
    #pragma unroll
    for (int o = 1; o < 64; o <<= 1) {
        int tmp = (t >= o) ? s[t - o] : 0;
        __syncthreads();
        s[t] += tmp;
        __syncthreads();
    }
    g_bsum[t] = s[t] - v;                        // exclusive block offsets
}

__global__ void scan3_kernel() {
    int i = blockIdx.x * 256 + threadIdx.x;
    if (i < Nn) {
        int off = g_offs[i] + g_bsum[i >> 10];
        g_offs[i] = off;
        g_cur[i]  = off;
    }
    if (i == 0) g_offs[Nn] = EPn;
}

__global__ void scatter_kernel(const int* __restrict__ src,
                               const int* __restrict__ dst,
                               const float* __restrict__ ew) {
    int e = blockIdx.x * 256 + threadIdx.x;
    if (e >= EPn) return;
    int s, d; float w;
    if (e < Ee) { s = src[e]; d = dst[e]; w = ew[e]; }
    else        { s = e - Ee; d = s;      w = g_meanw; }
    int pos = atomicAdd(&g_cur[d], 1);
    g_sedge[pos] = make_float2(__int_as_float(s), w);
}

// ---------------- GEMM: C[M,128] = A[M,128] @ W[128,128] ----------------
// block = 256 threads = 8 warps, 32 rows per block (R6 config, ~93% FFMA peak)
__global__ void gemm128(const float* __restrict__ A, const float* __restrict__ W,
                        float* __restrict__ C, int M)
{
    __shared__ float sW[32][128];
    __shared__ float sA[32][32];
    int t = threadIdx.x;
    int warp = t >> 5, lane = t & 31;
    int row0 = blockIdx.x * 32;
    float acc[4][4] = {};

    for (int k0 = 0; k0 < 128; k0 += 32) {
        #pragma unroll
        for (int kr = warp; kr < 32; kr += 8)
            *(float4*)&sW[kr][lane * 4] = *(const float4*)&W[(k0 + kr) * 128 + lane * 4];
        {
            int r  = t >> 3;
            int kk = (t & 7) * 4;
            int gr = row0 + r;
            float4 v = make_float4(0.f, 0.f, 0.f, 0.f);
            if (gr < M) v = *(const float4*)&A[(size_t)gr * 128 + k0 + kk];
            *(float4*)&sA[r][kk] = v;
        }
        __syncthreads();
        #pragma unroll
        for (int kk = 0; kk < 32; ++kk) {
            float w0 = sW[kk][lane];
            float w1 = sW[kk][32 + lane];
            float w2 = sW[kk][64 + lane];
            float w3 = sW[kk][96 + lane];
            #pragma unroll
            for (int i = 0; i < 4; ++i) {
                float a = sA[warp * 4 + i][kk];
                acc[i][0] += a * w0;
                acc[i][1] += a * w1;
                acc[i][2] += a * w2;
                acc[i][3] += a * w3;
            }
        }
        __syncthreads();
    }
    #pragma unroll
    for (int i = 0; i < 4; ++i) {
        int gr = row0 + warp * 4 + i;
        if (gr < M) {
            #pragma unroll
            for (int j = 0; j < 4; ++j)
                C[(size_t)gr * 128 + j * 32 + lane] = acc[i][j];
        }
    }
}

// ---------------- CSR GAT layer: one warp per dst, 4 edge-groups per warp -----
// 8 lanes per edge; lane owns features sl*16..sl*16+15 (sl = lane&7), so a
// lane's features live in head sl>>1. Group g (lane>>3) processes edges
// beg+g, beg+g+4, ... 4 independent edges in flight per warp (MLP x4), one
// pair-shuffle per edge for the logit, cross-group combine once per node.
template<int LAYER>
__global__ void gat_csr_kernel(const float* __restrict__ xl,
                               const float* __restrict__ xr,
                               const float* __restrict__ We,
                               const float* __restrict__ att,
                               const float* __restrict__ bias,
                               float* __restrict__ outp)
{
    __shared__ float sWe[128], sAtt[128];
    int t = threadIdx.x;
    if (t < 128) { sWe[t] = We[t]; sAtt[t] = att[t]; }
    __syncthreads();

    int d    = (blockIdx.x * 256 + t) >> 5;
    int lane = t & 31;
    if (d >= Nn) return;
    int grp = lane >> 3;          // edge group 0..3
    int sl  = lane & 7;           // sub-lane: owns elems sl*16 .. sl*16+15
    unsigned pairmask = 3u << (lane & 30);

    int beg = g_offs[d], end = g_offs[d + 1];

    float4 b[4], we[4], at[4];
    #pragma unroll
    for (int q = 0; q < 4; ++q) {
        b[q]  = *(const float4*)(xr + (size_t)d * 128 + sl * 16 + q * 4);
        we[q] = *(const float4*)&sWe [sl * 16 + q * 4];
        at[q] = *(const float4*)&sAtt[sl * 16 + q * 4];
    }

    float4 acc[4];
    #pragma unroll
    for (int q = 0; q < 4; ++q) acc[q] = make_float4(0.f, 0.f, 0.f, 0.f);
    float denom = 0.f;

    // depth-1 prefetch within this group's stride-4 edge stream
    int i = beg + grp;
    float2 eg = make_float2(0.f, 0.f);
    float4 a[4];
    if (i < end) {
        eg = g_sedge[i];
        const float* row = xl + (size_t)__float_as_int(eg.x) * 128 + sl * 16;
        #pragma unroll
        for (int q = 0; q < 4; ++q) a[q] = *(const float4*)(row + q * 4);
    }

    while (i < end) {
        float  w = eg.y;
        float4 ac[4] = {a[0], a[1], a[2], a[3]};
        int inext = i + 4;
        if (inext < end) {
            eg = g_sedge[inext];
            const float* row = xl + (size_t)__float_as_int(eg.x) * 128 + sl * 16;
            #pragma unroll
            for (int q = 0; q < 4; ++q) a[q] = *(const float4*)(row + q * 4);
        }

        float sum = 0.f;
        #pragma unroll
        for (int q = 0; q < 4; ++q) {
            float v0 = ac[q].x + b[q].x + w * we[q].x;
            float v1 = ac[q].y + b[q].y + w * we[q].y;
            float v2 = ac[q].z + b[q].z + w * we[q].z;
            float v3 = ac[q].w + b[q].w + w * we[q].w;
            v0 = v0 > 0.f ? v0 : 0.2f * v0;      // leaky_relu 0.2
            v1 = v1 > 0.f ? v1 : 0.2f * v1;
            v2 = v2 > 0.f ? v2 : 0.2f * v2;
            v3 = v3 > 0.f ? v3 : 0.2f * v3;
            sum += v0 * at[q].x + v1 * at[q].y + v2 * at[q].z + v3 * at[q].w;
        }
        // pair reduce: lanes sl, sl^1 own the two halves of head sl>>1
        sum += __shfl_xor_sync(pairmask, sum, 1);

        float p = __expf(sum);
        denom += p;
        #pragma unroll
        for (int q = 0; q < 4; ++q) {
            acc[q].x += p * ac[q].x;
            acc[q].y += p * ac[q].y;
            acc[q].z += p * ac[q].z;
            acc[q].w += p * ac[q].w;
        }
        i = inext;
    }

    // cross-group combine (sum the 4 edge groups)
    __syncwarp();
    #pragma unroll
    for (int o = 8; o <= 16; o <<= 1) {
        #pragma unroll
        for (int q = 0; q < 4; ++q) {
            acc[q].x += __shfl_xor_sync(0xffffffffu, acc[q].x, o);
            acc[q].y += __shfl_xor_sync(0xffffffffu, acc[q].y, o);
            acc[q].z += __shfl_xor_sync(0xffffffffu, acc[q].z, o);
            acc[q].w += __shfl_xor_sync(0xffffffffu, acc[q].w, o);
        }
        denom += __shfl_xor_sync(0xffffffffu, denom, o);
    }

    float inv = 1.f / (denom + 1e-16f);
    #pragma unroll
    for (int q = 0; q < 4; ++q) {
        acc[q].x *= inv; acc[q].y *= inv; acc[q].z *= inv; acc[q].w *= inv;
    }

    if (LAYER == 1) {
        if (grp == 0) {
            #pragma unroll
            for (int q = 0; q < 4; ++q) {
                float4 bb = *(const float4*)(bias + sl * 16 + q * 4);
                float r0 = acc[q].x + bb.x;
                float r1 = acc[q].y + bb.y;
                float r2 = acc[q].z + bb.z;
                float r3 = acc[q].w + bb.w;
                r0 = r0 > 0.f ? r0 : (__expf(r0) - 1.f);   // ELU
                r1 = r1 > 0.f ? r1 : (__expf(r1) - 1.f);
                r2 = r2 > 0.f ? r2 : (__expf(r2) - 1.f);
                r3 = r3 > 0.f ? r3 : (__expf(r3) - 1.f);
                *(float4*)(outp + (size_t)d * 128 + sl * 16 + q * 4) =
                    make_float4(r0, r1, r2, r3);
            }
        }
    } else {
        // mean over heads: channel c=(sl&1)*16+k lives at lanes sl, sl^2, sl^4, sl^6
        #pragma unroll
        for (int o = 2; o <= 4; o <<= 1) {
            #pragma unroll
            for (int q = 0; q < 4; ++q) {
                acc[q].x += __shfl_xor_sync(0xffffffffu, acc[q].x, o);
                acc[q].y += __shfl_xor_sync(0xffffffffu, acc[q].y, o);
                acc[q].z += __shfl_xor_sync(0xffffffffu, acc[q].z, o);
                acc[q].w += __shfl_xor_sync(0xffffffffu, acc[q].w, o);
            }
        }
        if (grp == 0 && sl < 2) {
            #pragma unroll
            for (int q = 0; q < 4; ++q) {
                float4 bb = *(const float4*)(bias + sl * 16 + q * 4);
                *(float4*)(outp + (size_t)d * 32 + sl * 16 + q * 4) =
                    make_float4(0.25f * acc[q].x + bb.x, 0.25f * acc[q].y + bb.y,
                                0.25f * acc[q].z + bb.z, 0.25f * acc[q].w + bb.w);
            }
        }
    }
}

// ---------------- launcher ----------------
extern "C" void kernel_launch(void* const* d_in, const int* in_sizes, int n_in,
                              void* d_out, int out_size)
{
    const float* x    = (const float*)d_in[0];
    const int*   ei   = (const int*)  d_in[1];
    const float* ew   = (const float*)d_in[2];
    const float* Wl1  = (const float*)d_in[3];
    const float* Wr1  = (const float*)d_in[4];
    const float* We1  = (const float*)d_in[5];
    const float* att1 = (const float*)d_in[6];
    const float* b1   = (const float*)d_in[7];
    const float* Wl2  = (const float*)d_in[8];
    const float* Wr2  = (const float*)d_in[9];
    const float* We2  = (const float*)d_in[10];
    const float* att2 = (const float*)d_in[11];
    const float* b2   = (const float*)d_in[12];
    float* out = (float*)d_out;

    const int* src = ei;
    const int* dst = ei + Ee;

    float *p_xl, *p_xr, *p_h;
    int* p_count;
    cudaGetSymbolAddress((void**)&p_xl,    g_xl);
    cudaGetSymbolAddress((void**)&p_xr,    g_xr);
    cudaGetSymbolAddress((void**)&p_h,     g_h);
    cudaGetSymbolAddress((void**)&p_count, g_count);

    const int gemmGrid = (Nn + 31) / 32;          // 1563
    const int edgeGrid = (EPn + 255) / 256;
    const int nodeGrid = (Nn * 32 + 255) / 256;   // warp per node
    const int nGrid    = (Nn + 255) / 256;

    // mean edge weight
    reduce_partial<<<1024, 256>>>(ew);
    reduce_final<<<1, 1024>>>();

    // CSR build (shared by both layers)
    cudaMemsetAsync(p_count, 0, Nn * sizeof(int));
    hist_kernel<<<edgeGrid, 256>>>(dst);
    scan1_kernel<<<NBLK, 1024>>>();
    scan2_kernel<<<1, 64>>>();
    scan3_kernel<<<nGrid, 256>>>();
    scatter_kernel<<<edgeGrid, 256>>>(src, dst, ew);

    // ---- layer 1 ----
    gemm128<<<gemmGrid, 256>>>(x, Wl1, p_xl, Nn);
    gemm128<<<gemmGrid, 256>>>(x, Wr1, p_xr, Nn);
    gat_csr_kernel<1><<<nodeGrid, 256>>>(p_xl, p_xr, We1, att1, b1, p_h);

    // ---- layer 2 ----
    gemm128<<<gemmGrid, 256>>>(p_h, Wl2, p_xl, Nn);
    gemm128<<<gemmGrid, 256>>>(p_h, Wr2, p_xr, Nn);
    gat_csr_kernel<2><<<nodeGrid, 256>>>(p_xl, p_xr, We2, att2, b2, out);
}

// round 14
// speedup vs baseline: 1.2752x; 1.2752x over previous
#include <cuda_runtime.h>
#include <math.h>
#include <stdint.h>

#define Nn 50000
#define Ee 1600000
#define EPn 1650000   // Ee + Nn (self loops appended)
#define F 128         // H*C = 4*32
#define NBLK 49       // ceil(Nn/1024) for scan

// ---------------- scratch (static device memory; no allocation) ----------------
__device__ float    g_xl [(size_t)Nn * F];
__device__ float    g_xr [(size_t)Nn * F];
__device__ float    g_h  [(size_t)Nn * F];
__device__ int      g_count[Nn];
__device__ int      g_offs [Nn + 1];
__device__ int      g_cur  [Nn];
__device__ int      g_bsum [64];
__device__ float2   g_sedge[EPn];      // sorted (src_as_float_bits, weight)
__device__ float    g_wsum;
__device__ float    g_meanw;

// ---------------- side stream + fork/join events (host objects, static init) ---
struct Aux {
    cudaStream_t s2;
    cudaEvent_t  eFork, eJoin;
    Aux() {
        cudaStreamCreateWithFlags(&s2, cudaStreamNonBlocking);
        cudaEventCreateWithFlags(&eFork, cudaEventDisableTiming);
        cudaEventCreateWithFlags(&eJoin, cudaEventDisableTiming);
    }
};
static Aux g_aux;

// ---------------- CSR build: histogram (+ew sum) -> scan -> scatter ------------
__global__ void hist_kernel(const int* __restrict__ dst,
                            const float* __restrict__ ew) {
    __shared__ float s[256];
    int e = blockIdx.x * 256 + threadIdx.x;
    float w = 0.f;
    if (e < EPn) {
        int d;
        if (e < Ee) { d = dst[e]; w = ew[e]; }
        else        { d = e - Ee; }
        atomicAdd(&g_count[d], 1);
    }
    s[threadIdx.x] = w;
    __syncthreads();
    for (int o = 128; o > 0; o >>= 1) {
        if (threadIdx.x < o) s[threadIdx.x] += s[threadIdx.x + o];
        __syncthreads();
    }
    if (threadIdx.x == 0) atomicAdd(&g_wsum, s[0]);
}

__global__ void scan1_kernel() {      // grid NBLK, block 1024
    __shared__ int s[1024];
    int t = threadIdx.x;
    int i = blockIdx.x * 1024 + t;
    int v = (i < Nn) ? g_count[i] : 0;
    s[t] = v;
    __syncthreads();
    #pragma unroll
    for (int o = 1; o < 1024; o <<= 1) {
        int tmp = (t >= o) ? s[t - o] : 0;
        __syncthreads();
        s[t] += tmp;
        __syncthreads();
    }
    if (i < Nn) g_offs[i] = s[t] - v;           // exclusive within block
    if (t == 1023) g_bsum[blockIdx.x] = s[1023];
}

__global__ void scan2_kernel() {      // 1 block, 64 threads (+ meanw finalize)
    __shared__ int s[64];
    int t = threadIdx.x;
    int v = (t < NBLK) ? g_bsum[t] : 0;
    s[t] = v;
    __syncthreads();
    #pragma unroll
    for (int o = 1; o < 64; o <<= 1) {
        int tmp = (t >= o) ? s[t - o] : 0;
        __syncthreads();
        s[t] += tmp;
        __syncthreads();
    }
    g_bsum[t] = s[t] - v;                        // exclusive block offsets
    if (t == 0) g_meanw = g_wsum * (1.f / (float)Ee);
}

__global__ void scan3_kernel() {
    int i = blockIdx.x * 256 + threadIdx.x;
    if (i < Nn) {
        int off = g_offs[i] + g_bsum[i >> 10];
        g_offs[i] = off;
        g_cur[i]  = off;
    }
    if (i == 0) g_offs[Nn] = EPn;
}

__global__ void scatter_kernel(const int* __restrict__ src,
                               const int* __restrict__ dst,
                               const float* __restrict__ ew) {
    int e = blockIdx.x * 256 + threadIdx.x;
    if (e >= EPn) return;
    int s, d; float w;
    if (e < Ee) { s = src[e]; d = dst[e]; w = ew[e]; }
    else        { s = e - Ee; d = s;      w = g_meanw; }
    int pos = atomicAdd(&g_cur[d], 1);
    g_sedge[pos] = make_float2(__int_as_float(s), w);
}

// ---------------- GEMM: C[M,128] = A[M,128] @ W[128,128] ----------------
// block = 256 threads = 8 warps, 32 rows per block (~93% of FFMA issue peak)
__global__ void gemm128(const float* __restrict__ A, const float* __restrict__ W,
                        float* __restrict__ C, int M)
{
    __shared__ float sW[32][128];
    __shared__ float sA[32][32];
    int t = threadIdx.x;
    int warp = t >> 5, lane = t & 31;
    int row0 = blockIdx.x * 32;
    float acc[4][4] = {};

    for (int k0 = 0; k0 < 128; k0 += 32) {
        #pragma unroll
        for (int kr = warp; kr < 32; kr += 8)
            *(float4*)&sW[kr][lane * 4] = *(const float4*)&W[(k0 + kr) * 128 + lane * 4];
        {
            int r  = t >> 3;
            int kk = (t & 7) * 4;
            int gr = row0 + r;
            float4 v = make_float4(0.f, 0.f, 0.f, 0.f);
            if (gr < M) v = *(const float4*)&A[(size_t)gr * 128 + k0 + kk];
            *(float4*)&sA[r][kk] = v;
        }
        __syncthreads();
        #pragma unroll
        for (int kk = 0; kk < 32; ++kk) {
            float w0 = sW[kk][lane];
            float w1 = sW[kk][32 + lane];
            float w2 = sW[kk][64 + lane];
            float w3 = sW[kk][96 + lane];
            #pragma unroll
            for (int i = 0; i < 4; ++i) {
                float a = sA[warp * 4 + i][kk];
                acc[i][0] += a * w0;
                acc[i][1] += a * w1;
                acc[i][2] += a * w2;
                acc[i][3] += a * w3;
            }
        }
        __syncthreads();
    }
    #pragma unroll
    for (int i = 0; i < 4; ++i) {
        int gr = row0 + warp * 4 + i;
        if (gr < M) {
            #pragma unroll
            for (int j = 0; j < 4; ++j)
                C[(size_t)gr * 128 + j * 32 + lane] = acc[i][j];
        }
    }
}

// ---------------- CSR GAT layer: one warp per destination node ----------------
// R6 shape: lane owns features lane*4..lane*4+3 (head = lane>>3), depth-1
// prefetch, register accumulation, fused epilogue. ~40 regs/thread.
template<int LAYER>
__global__ void gat_csr_kernel(const float* __restrict__ xl,
                               const float* __restrict__ xr,
                               const float* __restrict__ We,
                               const float* __restrict__ att,
                               const float* __restrict__ bias,
                               float* __restrict__ outp)
{
    __shared__ float sWe[128], sAtt[128];
    int t = threadIdx.x;
    if (t < 128) { sWe[t] = We[t]; sAtt[t] = att[t]; }
    __syncthreads();

    int d    = (blockIdx.x * 256 + t) >> 5;
    int lane = t & 31;
    if (d >= Nn) return;

    int beg = g_offs[d], end = g_offs[d + 1];

    float4 b  = *(const float4*)(xr + (size_t)d * 128 + lane * 4);
    float4 we = *(const float4*)&sWe [lane * 4];
    float4 at = *(const float4*)&sAtt[lane * 4];

    float4 acc = make_float4(0.f, 0.f, 0.f, 0.f);
    float denom = 0.f;

    float2 eg = g_sedge[beg];                    // beg < end always (self-loop)
    float4 a  = *(const float4*)(xl + (size_t)__float_as_int(eg.x) * 128 + lane * 4);

    for (int i = beg; i < end; ++i) {
        float  w    = eg.y;
        float4 acur = a;
        if (i + 1 < end) {
            eg = g_sedge[i + 1];
            a  = *(const float4*)(xl + (size_t)__float_as_int(eg.x) * 128 + lane * 4);
        }
        float v0 = acur.x + b.x + w * we.x;
        float v1 = acur.y + b.y + w * we.y;
        float v2 = acur.z + b.z + w * we.z;
        float v3 = acur.w + b.w + w * we.w;
        v0 = v0 > 0.f ? v0 : 0.2f * v0;          // leaky_relu 0.2
        v1 = v1 > 0.f ? v1 : 0.2f * v1;
        v2 = v2 > 0.f ? v2 : 0.2f * v2;
        v3 = v3 > 0.f ? v3 : 0.2f * v3;
        float sum = v0 * at.x + v1 * at.y + v2 * at.z + v3 * at.w;

        sum += __shfl_xor_sync(0xffffffffu, sum, 1);
        sum += __shfl_xor_sync(0xffffffffu, sum, 2);
        sum += __shfl_xor_sync(0xffffffffu, sum, 4);

        float p = __expf(sum);
        denom += p;
        acc.x += p * acur.x;
        acc.y += p * acur.y;
        acc.z += p * acur.z;
        acc.w += p * acur.w;
    }

    float inv = 1.f / (denom + 1e-16f);
    float r0 = acc.x * inv, r1 = acc.y * inv, r2 = acc.z * inv, r3 = acc.w * inv;

    if (LAYER == 1) {
        float4 bb = *(const float4*)(bias + lane * 4);
        r0 += bb.x; r1 += bb.y; r2 += bb.z; r3 += bb.w;
        r0 = r0 > 0.f ? r0 : (__expf(r0) - 1.f);   // ELU
        r1 = r1 > 0.f ? r1 : (__expf(r1) - 1.f);
        r2 = r2 > 0.f ? r2 : (__expf(r2) - 1.f);
        r3 = r3 > 0.f ? r3 : (__expf(r3) - 1.f);
        *(float4*)(outp + (size_t)d * 128 + lane * 4) = make_float4(r0, r1, r2, r3);
    } else {
        #pragma unroll
        for (int o = 8; o <= 16; o <<= 1) {
            r0 += __shfl_xor_sync(0xffffffffu, r0, o);
            r1 += __shfl_xor_sync(0xffffffffu, r1, o);
            r2 += __shfl_xor_sync(0xffffffffu, r2, o);
            r3 += __shfl_xor_sync(0xffffffffu, r3, o);
        }
        if (lane < 8) {
            float4 bb = *(const float4*)(bias + lane * 4);
            *(float4*)(outp + (size_t)d * 32 + lane * 4) =
                make_float4(0.25f * r0 + bb.x, 0.25f * r1 + bb.y,
                            0.25f * r2 + bb.z, 0.25f * r3 + bb.w);
        }
    }
}

// ---------------- launcher ----------------
extern "C" void kernel_launch(void* const* d_in, const int* in_sizes, int n_in,
                              void* d_out, int out_size)
{
    const float* x    = (const float*)d_in[0];
    const int*   ei   = (const int*)  d_in[1];
    const float* ew   = (const float*)d_in[2];
    const float* Wl1  = (const float*)d_in[3];
    const float* Wr1  = (const float*)d_in[4];
    const float* We1  = (const float*)d_in[5];
    const float* att1 = (const float*)d_in[6];
    const float* b1   = (const float*)d_in[7];
    const float* Wl2  = (const float*)d_in[8];
    const float* Wr2  = (const float*)d_in[9];
    const float* We2  = (const float*)d_in[10];
    const float* att2 = (const float*)d_in[11];
    const float* b2   = (const float*)d_in[12];
    float* out = (float*)d_out;

    const int* src = ei;
    const int* dst = ei + Ee;

    float *p_xl, *p_xr, *p_h, *p_wsum;
    int* p_count;
    cudaGetSymbolAddress((void**)&p_xl,    g_xl);
    cudaGetSymbolAddress((void**)&p_xr,    g_xr);
    cudaGetSymbolAddress((void**)&p_h,     g_h);
    cudaGetSymbolAddress((void**)&p_count, g_count);
    cudaGetSymbolAddress((void**)&p_wsum,  g_wsum);

    const int gemmGrid = (Nn + 31) / 32;          // 1563
    const int edgeGrid = (EPn + 255) / 256;
    const int nodeGrid = (Nn * 32 + 255) / 256;   // warp per node
    const int nGrid    = (Nn + 255) / 256;

    cudaStream_t s2 = g_aux.s2;

    // ---- fork: CSR build + meanw on side stream, overlapped with L1 GEMMs ----
    cudaEventRecord(g_aux.eFork, 0);
    cudaStreamWaitEvent(s2, g_aux.eFork, 0);

    cudaMemsetAsync(p_count, 0, Nn * sizeof(int), s2);
    cudaMemsetAsync(p_wsum,  0, sizeof(float),    s2);
    hist_kernel   <<<edgeGrid, 256, 0, s2>>>(dst, ew);
    scan1_kernel  <<<NBLK, 1024, 0, s2>>>();
    scan2_kernel  <<<1, 64, 0, s2>>>();
    scan3_kernel  <<<nGrid, 256, 0, s2>>>();
    scatter_kernel<<<edgeGrid, 256, 0, s2>>>(src, dst, ew);
    cudaEventRecord(g_aux.eJoin, s2);

    // ---- layer 1 GEMMs on main stream (overlap with CSR build) ----
    gemm128<<<gemmGrid, 256>>>(x, Wl1, p_xl, Nn);
    gemm128<<<gemmGrid, 256>>>(x, Wr1, p_xr, Nn);

    // ---- join, then layer 1 aggregation ----
    cudaStreamWaitEvent(0, g_aux.eJoin, 0);
    gat_csr_kernel<1><<<nodeGrid, 256>>>(p_xl, p_xr, We1, att1, b1, p_h);

    // ---- layer 2 ----
    gemm128<<<gemmGrid, 256>>>(p_h, Wl2, p_xl, Nn);
    gemm128<<<gemmGrid, 256>>>(p_h, Wr2, p_xr, Nn);
    gat_csr_kernel<2><<<nodeGrid, 256>>>(p_xl, p_xr, We2, att2, b2, out);
}